// round 10
// baseline (speedup 1.0000x reference)
#include <cuda_runtime.h>
#include <cstdint>

// CTC loss, probability-domain forward DP, per-lane block-float exponents.
// R10: warp-specialized producer/consumer. Producer warp streams rows via
// cp.async + mbarrier (runs up to 11 chunks ahead, paced only by empty
// barriers); consumer warp does LDS gather + the DP chain. Decouples the
// DRAM request stream from the DP cadence and doubles warps/SMSP.
// B=512, T=512, C=128, L=64, S=129, blank=127.

#define CTC_B 512
#define CTC_T 512
#define CTC_C 128
#define CTC_L 64
#define CH    8                 // rows per chunk = rescale period
#define RCH   11                // ring slots (44 KB)
#define NCH   (CTC_T / CH)      // 64 chunks

__device__ __forceinline__ void mbar_wait(uint64_t* bar, int phase) {
    unsigned addr = (unsigned)__cvta_generic_to_shared(bar);
    asm volatile(
        "{\n\t"
        ".reg .pred P;\n\t"
        "W_%=:\n\t"
        "mbarrier.try_wait.parity.acquire.cta.shared::cta.b64 P, [%0], %1, 0x989680;\n\t"
        "@P bra D_%=;\n\t"
        "bra W_%=;\n\t"
        "D_%=:\n\t"
        "}" :: "r"(addr), "r"(phase) : "memory");
}

__device__ __forceinline__ void mbar_arrive(uint64_t* bar) {
    unsigned addr = (unsigned)__cvta_generic_to_shared(bar);
    asm volatile("mbarrier.arrive.shared.b64 _, [%0];" :: "r"(addr) : "memory");
}

__global__ __launch_bounds__(64) void ctc_kernel(
    const int* __restrict__ y_true,
    const float* __restrict__ y_pred,
    float* __restrict__ out)
{
    __shared__ float ring[RCH * CH * CTC_C];     // 44 KB
    __shared__ uint64_t fullb[RCH], emptyb[RCH]; // per-slot barriers

    const float EPS = 1e-7f;
    const unsigned FULL = 0xffffffffu;
    const int b    = blockIdx.x;
    const int tid  = threadIdx.x;
    const int lane = tid & 31;
    const int wid  = tid >> 5;    // 0 = consumer (DP), 1 = producer (loads)

    if (tid == 0) {
#pragma unroll
        for (int s = 0; s < RCH; ++s) {
            unsigned fa = (unsigned)__cvta_generic_to_shared(&fullb[s]);
            unsigned ea = (unsigned)__cvta_generic_to_shared(&emptyb[s]);
            asm volatile("mbarrier.init.shared.b64 [%0], 32;" :: "r"(fa));
            asm volatile("mbarrier.init.shared.b64 [%0], 32;" :: "r"(ea));
        }
    }
    __syncthreads();

    const float* base = y_pred + (size_t)b * CTC_T * CTC_C;

    if (wid == 1) {
        // ---------------- producer warp ----------------
        const unsigned smb = (unsigned)__cvta_generic_to_shared(ring);
        const unsigned lane4 = 4u * (unsigned)lane;
        int slot = 0, n = 0;   // n = completed ring cycles
        for (int c = 0; c < NCH; ++c) {
            if (n) mbar_wait(&emptyb[slot], (n - 1) & 1);
            const unsigned sbase = (unsigned)slot * (CH * CTC_C);
#pragma unroll
            for (int r = 0; r < CH; ++r) {
                const float* src = base + (size_t)(c * CH + r) * CTC_C + lane4;
                const unsigned dst = smb + (sbase + (unsigned)r * CTC_C + lane4) * 4u;
                asm volatile("cp.async.cg.shared.global [%0], [%1], 16;"
                             :: "r"(dst), "l"(src));
            }
            {   // async arrival on full[slot] when this lane's cp.asyncs land
                unsigned fa = (unsigned)__cvta_generic_to_shared(&fullb[slot]);
                asm volatile("cp.async.mbarrier.arrive.noinc.shared.b64 [%0];"
                             :: "r"(fa) : "memory");
            }
            if (++slot == RCH) { slot = 0; ++n; }
        }
        return;
    }

    // ---------------- consumer warp ----------------
    const int* lrow = y_true + b * CTC_L;
    const int lab1 = lrow[2 * lane];
    const int lab3 = lrow[2 * lane + 1];
    const int prev1 = (lane > 0) ? lrow[2 * lane - 1] : -1;
    const bool allow1 = (lane > 0) && (lab1 != prev1);
    const bool allow3 = (lab3 != lab1);

    float a0 = (lane == 0) ? 1.0f : 0.0f;   // virtual pre-init (yields ref t=0)
    float a1 = 0.0f, a2 = 0.0f, a3 = 0.0f, a4 = 0.0f;
    int   E  = 0;                            // alpha = a * 2^E (per lane)
    float f  = (lane == 0) ? 0.0f : 1.0f;    // neighbor re-basing factor

    int slot = 0, n = 0;
    for (int c = 0; c < NCH; ++c) {
        mbar_wait(&fullb[slot], n & 1);

        // gather the 3 needed probs for all 8 rows (LDS), then free the slot
        const int cb = slot * (CH * CTC_C);
        float pb[CH], p1[CH], p3[CH];
#pragma unroll
        for (int j = 0; j < CH; ++j) {
            const int rb = cb + j * CTC_C;
            pb[j] = ring[rb + (CTC_C - 1)] + EPS;
            p1[j] = ring[rb + lab1] + EPS;
            p3[j] = ring[rb + lab3] + EPS;
        }
        mbar_arrive(&emptyb[slot]);   // release: gathers are ordered before this

        // 8 DP steps (pure FADD/FMUL + 1 shfl each)
#pragma unroll
        for (int j = 0; j < CH; ++j) {
            const float am1 = __shfl_up_sync(FULL, a3, 1) * f;   // lane0: f=0

            const float n0 = (a0 + am1) * pb[j];                          // s=4l (blank)
            const float n1 = (a1 + a0 + (allow1 ? am1 : 0.0f)) * p1[j];   // s=4l+1
            const float n2 = (a2 + a1) * pb[j];                           // s=4l+2
            const float n3 = (a3 + a2 + (allow3 ? a1 : 0.0f)) * p3[j];    // s=4l+3
            const float n4 = (a4 + a3) * pb[j];                           // s=128 (lane31)
            a0 = n0; a1 = n1; a2 = n2; a3 = n3; a4 = n4;
        }

        // ---- per-lane power-of-2 rescale (every 8 steps) ----
        {
            float lm = fmaxf(fmaxf(a0, a1), fmaxf(a2, a3));
            lm = fmaxf(lm, a4);
            int e = (int)(__float_as_uint(lm) >> 23) - 127;
            const bool zero = (lm == 0.0f);
            if (zero) e = 0;
            const float sc = __uint_as_float((unsigned)(127 - e) << 23); // 2^-e
            a0 *= sc; a1 *= sc; a2 *= sc; a3 *= sc; a4 *= sc;
            E += e;
            const int Ep = __shfl_up_sync(FULL, E, 1);
            if (zero && lane > 0) E = Ep;     // adopt neighbor frame ahead of wavefront
            const int Ep2 = __shfl_up_sync(FULL, E, 1);
            int d = Ep2 - E;
            d = max(-126, min(126, d));
            f = __uint_as_float((unsigned)(127 + d) << 23);  // 2^d
            if (lane == 0) f = 0.0f;
        }

        if (++slot == RCH) { slot = 0; ++n; }
    }

    if (lane == 31) {
        // P_total = alpha_{T-1}[S-1] + alpha_{T-1}[S-2] = (a4 + a3) * 2^E
        const float p = a4 + a3;
        out[b] = -(__logf(p) + (float)E * 0.69314718055994530942f);
    }
}

extern "C" void kernel_launch(void* const* d_in, const int* in_sizes, int n_in,
                              void* d_out, int out_size) {
    const int*   y_true = (const int*)d_in[0];
    const float* y_pred = (const float*)d_in[1];
    float*       outp   = (float*)d_out;
    (void)in_sizes; (void)n_in; (void)out_size;

    ctc_kernel<<<CTC_B, 64>>>(y_true, y_pred, outp);
}

// round 11
// speedup vs baseline: 1.1509x; 1.1509x over previous
#include <cuda_runtime.h>
#include <cstdint>

// CTC loss, probability-domain forward DP, per-lane block-float exponents.
// R11: TMA bulk streaming. Each 16-row chunk (8KB, contiguous in gmem) is
// fetched by ONE cp.async.bulk (UBLKCP) completing on a per-slot mbarrier --
// requests queue in the TMA engine instead of the per-SM LSU/L1tex queues
// that capped every LDGSTS variant at ~5.4 TB/s.
// B=512, T=512, C=128, L=64, S=129, blank=127. One warp per batch element.

#define CTC_B 512
#define CTC_T 512
#define CTC_C 128
#define CTC_L 64
#define CH    16                // rows per chunk (8 KB)
#define RS    8                 // rescale period (steps)
#define RCH   6                 // ring slots (48 KB smem)
#define LA    (RCH - 1)         // chunks in flight (5 -> 40 KB)
#define NCH   (CTC_T / CH)      // 32 chunks
#define CHUNK_BYTES (CH * CTC_C * 4)   // 8192

__device__ __forceinline__ void mbar_wait(uint64_t* bar, int phase) {
    unsigned addr = (unsigned)__cvta_generic_to_shared(bar);
    asm volatile(
        "{\n\t"
        ".reg .pred P;\n\t"
        "W_%=:\n\t"
        "mbarrier.try_wait.parity.acquire.cta.shared::cta.b64 P, [%0], %1, 0x989680;\n\t"
        "@P bra D_%=;\n\t"
        "bra W_%=;\n\t"
        "D_%=:\n\t"
        "}" :: "r"(addr), "r"(phase) : "memory");
}

__global__ __launch_bounds__(32) void ctc_kernel(
    const int* __restrict__ y_true,
    const float* __restrict__ y_pred,
    float* __restrict__ out)
{
    __shared__ __align__(128) float ring[RCH * CH * CTC_C];   // 48 KB
    __shared__ uint64_t fullb[RCH];

    const float EPS = 1e-7f;
    const unsigned FULL = 0xffffffffu;
    const int b    = blockIdx.x;
    const int lane = threadIdx.x;

    if (lane == 0) {
#pragma unroll
        for (int s = 0; s < RCH; ++s) {
            unsigned fa = (unsigned)__cvta_generic_to_shared(&fullb[s]);
            asm volatile("mbarrier.init.shared.b64 [%0], 1;" :: "r"(fa));
        }
        asm volatile("fence.proxy.async.shared::cta;" ::: "memory");
    }
    __syncwarp();

    const int* lrow = y_true + b * CTC_L;
    const int lab1 = lrow[2 * lane];
    const int lab3 = lrow[2 * lane + 1];
    const int prev1 = (lane > 0) ? lrow[2 * lane - 1] : -1;
    const bool allow1 = (lane > 0) && (lab1 != prev1);
    const bool allow3 = (lab3 != lab1);

    const float* base = y_pred + (size_t)b * CTC_T * CTC_C;
    const unsigned smb = (unsigned)__cvta_generic_to_shared(ring);

    // One bulk copy per chunk, issued by lane 0, completes on fullb[slot].
    auto issue_chunk = [&](int c, int slot) {
        if (lane == 0) {
            const unsigned fa  = (unsigned)__cvta_generic_to_shared(&fullb[slot]);
            const unsigned dst = smb + (unsigned)slot * CHUNK_BYTES;
            const float*   src = base + (size_t)c * (CH * CTC_C);
            asm volatile("mbarrier.arrive.expect_tx.shared.b64 _, [%0], %1;"
                         :: "r"(fa), "r"(CHUNK_BYTES) : "memory");
            asm volatile(
                "cp.async.bulk.shared::cluster.global.mbarrier::complete_tx::bytes"
                " [%0], [%1], %2, [%3];"
                :: "r"(dst), "l"(src), "r"(CHUNK_BYTES), "r"(fa) : "memory");
        }
    };

    // Prologue: fill LA chunks (slots 0..LA-1).
#pragma unroll
    for (int c = 0; c < LA; ++c) issue_chunk(c, c);

    float a0 = (lane == 0) ? 1.0f : 0.0f;   // virtual pre-init (yields ref t=0)
    float a1 = 0.0f, a2 = 0.0f, a3 = 0.0f, a4 = 0.0f;
    int   E  = 0;                            // alpha = a * 2^E (per lane)
    float f  = (lane == 0) ? 0.0f : 1.0f;    // neighbor re-basing factor

    int rslot = 0, rphase = 0;   // slot/parity of chunk c
    int wslot = LA;              // slot for chunk c+LA (last read in iter c-1)

    for (int c = 0; c < NCH; ++c) {
        if (c + LA < NCH) issue_chunk(c + LA, wslot);

        mbar_wait(&fullb[rslot], rphase);   // chunk c resident + visible

        // Gather the 3 needed probs for all 16 rows of this chunk (LDS).
        const int cb = rslot * (CH * CTC_C);
        float pb[CH], p1[CH], p3[CH];
#pragma unroll
        for (int j = 0; j < CH; ++j) {
            const int rb = cb + j * CTC_C;
            pb[j] = ring[rb + (CTC_C - 1)] + EPS;
            p1[j] = ring[rb + lab1] + EPS;
            p3[j] = ring[rb + lab3] + EPS;
        }

        // 16 DP steps; per-lane power-of-2 rescale every 8.
#pragma unroll
        for (int j = 0; j < CH; ++j) {
            const float am1 = __shfl_up_sync(FULL, a3, 1) * f;   // lane0: f=0

            const float n0 = (a0 + am1) * pb[j];                          // s=4l (blank)
            const float n1 = (a1 + a0 + (allow1 ? am1 : 0.0f)) * p1[j];   // s=4l+1
            const float n2 = (a2 + a1) * pb[j];                           // s=4l+2
            const float n3 = (a3 + a2 + (allow3 ? a1 : 0.0f)) * p3[j];    // s=4l+3
            const float n4 = (a4 + a3) * pb[j];                           // s=128 (lane31)
            a0 = n0; a1 = n1; a2 = n2; a3 = n3; a4 = n4;

            if ((j & (RS - 1)) == (RS - 1)) {
                float lm = fmaxf(fmaxf(a0, a1), fmaxf(a2, a3));
                lm = fmaxf(lm, a4);
                int e = (int)(__float_as_uint(lm) >> 23) - 127;
                const bool zero = (lm == 0.0f);
                if (zero) e = 0;
                const float sc = __uint_as_float((unsigned)(127 - e) << 23); // 2^-e
                a0 *= sc; a1 *= sc; a2 *= sc; a3 *= sc; a4 *= sc;
                E += e;
                const int Ep = __shfl_up_sync(FULL, E, 1);
                if (zero && lane > 0) E = Ep;   // adopt neighbor frame ahead of wavefront
                const int Ep2 = __shfl_up_sync(FULL, E, 1);
                int d = Ep2 - E;
                d = max(-126, min(126, d));
                f = __uint_as_float((unsigned)(127 + d) << 23);  // 2^d
                if (lane == 0) f = 0.0f;
            }
        }

        if (++rslot == RCH) { rslot = 0; rphase ^= 1; }
        if (++wslot == RCH) wslot = 0;
    }

    if (lane == 31) {
        // P_total = alpha_{T-1}[S-1] + alpha_{T-1}[S-2] = (a4 + a3) * 2^E
        const float p = a4 + a3;
        out[b] = -(__logf(p) + (float)E * 0.69314718055994530942f);
    }
}

extern "C" void kernel_launch(void* const* d_in, const int* in_sizes, int n_in,
                              void* d_out, int out_size) {
    const int*   y_true = (const int*)d_in[0];
    const float* y_pred = (const float*)d_in[1];
    float*       outp   = (float*)d_out;
    (void)in_sizes; (void)n_in; (void)out_size;

    ctc_kernel<<<CTC_B, 32>>>(y_true, y_pred, outp);
}